// round 16
// baseline (speedup 1.0000x reference)
#include <cuda_runtime.h>
#include <cuda_fp16.h>

// ============================================================================
// Conv1Dfft via packed-real four-step FFT (M = 65536 = 256 x 256),
// register 16x16 FFT, fp16 global + fp16 smem intermediates, f32x2 math.
// Forward pass2 unpacks to rfft bins in-block; W spectrum synthesized in
// pass2; inverse pass1 mirror-shares g_So reads via paired columns.
// ============================================================================

#define M_FFT   65536
#define KEEP    32769          // bins 0..32768 kept (== M/2+1)
#define NROWS_X 256            // 32 n * 8 c
#define NROWS_W 128            // 16 f * 8 c
#define NROWS_F 384
#define NROWS_O 512            // 32 n * 16 f
#define OUT_W   65409

// ---------------- scratch (device globals; allocation-free) ----------------
__device__ __half2 g_Sx[(size_t)NROWS_F * KEEP];   // unpacked fwd spectra X
__device__ __half2 g_B[(size_t)NROWS_O * M_FFT];   // pass1 out (x fwd + inverse)
__device__ __half2 g_So[(size_t)NROWS_O * KEEP];   // product spectra
__device__ float2 g_twM[M_FFT];                    // e^{-2pi i j / 65536}
__device__ float2 g_tw2M[M_FFT];                   // e^{-2pi i j / 131072}

// ---------------- packed f32x2 complex helpers -----------------------------
static __device__ __forceinline__ float2 padd(float2 a, float2 b) {
    unsigned long long ua, ub, ur;
    asm("mov.b64 %0, {%1,%2};" : "=l"(ua) : "f"(a.x), "f"(a.y));
    asm("mov.b64 %0, {%1,%2};" : "=l"(ub) : "f"(b.x), "f"(b.y));
    asm("add.rn.f32x2 %0, %1, %2;" : "=l"(ur) : "l"(ua), "l"(ub));
    float2 o;
    asm("mov.b64 {%0,%1}, %2;" : "=f"(o.x), "=f"(o.y) : "l"(ur));
    return o;
}
static __device__ __forceinline__ float2 psub(float2 a, float2 b) {
    unsigned long long ua, ub, ur;
    const unsigned long long NEG1 = 0xBF800000BF800000ULL;  // (-1.f, -1.f)
    asm("mov.b64 %0, {%1,%2};" : "=l"(ua) : "f"(a.x), "f"(a.y));
    asm("mov.b64 %0, {%1,%2};" : "=l"(ub) : "f"(b.x), "f"(b.y));
    asm("fma.rn.f32x2 %0, %1, %2, %3;" : "=l"(ur) : "l"(ub), "l"(NEG1), "l"(ua));
    float2 o;
    asm("mov.b64 {%0,%1}, %2;" : "=f"(o.x), "=f"(o.y) : "l"(ur));
    return o;
}
static __device__ __forceinline__ float2 cmul(float2 a, float2 b) {
    return make_float2(fmaf(a.x, b.x, -(a.y * b.y)),
                       fmaf(a.x, b.y,   a.y * b.x));
}
static __device__ __forceinline__ float2 ldc(const __half2* p) {
    return __half22float2(*p);
}
static __device__ __forceinline__ void stc(__half2* p, float2 v) {
    *p = __float22half2_rn(v);
}

// ---------------- twiddle tables (fp32 sincospif, exact args) --------------
__global__ void k_init_tw() {
    int i = blockIdx.x * blockDim.x + threadIdx.x;
    if (i < M_FFT) {
        float s, c;
        sincospif(-(float)i / 32768.0f, &s, &c);
        g_twM[i] = make_float2(c, s);
        sincospif(-(float)i / 65536.0f, &s, &c);
        g_tw2M[i] = make_float2(c, s);
    }
}

// ---------------- 4-pt DFT on packed complex -------------------------------
static __device__ __forceinline__ void dft4(float2 x0, float2 x1, float2 x2,
                                            float2 x3, float2& y0, float2& y1,
                                            float2& y2, float2& y3) {
    float2 s0 = padd(x0, x2);
    float2 d0 = psub(x0, x2);
    float2 s1 = padd(x1, x3);
    float2 d1 = psub(x1, x3);
    y0 = padd(s0, s1);
    y2 = psub(s0, s1);
    float2 sw = make_float2(d1.y, -d1.x);   // -i*d1
    y1 = padd(d0, sw);
    y3 = psub(d0, sw);
}

// ---------------- 16-pt DFT in registers (radix-4 x radix-4) ---------------
__device__ __forceinline__ void fft16(float2 r[16]) {
    const float C1 = 0.9238795325112867f;
    const float S1 = 0.3826834323650898f;
    const float R2 = 0.7071067811865476f;
    float2 t[16];
    {
        float2 y0, y1, y2, y3;
        dft4(r[0], r[4], r[8], r[12], y0, y1, y2, y3);
        t[0] = y0; t[4] = y1; t[8] = y2; t[12] = y3;
    }
    {
        float2 y0, y1, y2, y3;
        dft4(r[1], r[5], r[9], r[13], y0, y1, y2, y3);
        t[1]  = y0;
        t[5]  = cmul(y1, make_float2( C1, -S1));
        t[9]  = cmul(y2, make_float2( R2, -R2));
        t[13] = cmul(y3, make_float2( S1, -C1));
    }
    {
        float2 y0, y1, y2, y3;
        dft4(r[2], r[6], r[10], r[14], y0, y1, y2, y3);
        t[2]  = y0;
        t[6]  = cmul(y1, make_float2( R2, -R2));
        t[10] = make_float2( y2.y, -y2.x);
        t[14] = cmul(y3, make_float2(-R2, -R2));
    }
    {
        float2 y0, y1, y2, y3;
        dft4(r[3], r[7], r[11], r[15], y0, y1, y2, y3);
        t[3]  = y0;
        t[7]  = cmul(y1, make_float2( S1, -C1));
        t[11] = cmul(y2, make_float2(-R2, -R2));
        t[15] = cmul(y3, make_float2(-C1,  S1));
    }
    #pragma unroll
    for (int p1 = 0; p1 < 4; p1++) {
        float2 y0, y1, y2, y3;
        dft4(t[4 * p1], t[4 * p1 + 1], t[4 * p1 + 2], t[4 * p1 + 3],
             y0, y1, y2, y3);
        r[p1] = y0; r[4 + p1] = y1; r[8 + p1] = y2; r[12 + p1] = y3;
    }
}

// pad-17 smem slot for pass-kernel tiles
#define SMI(u, c) ((u) * 17 + (c))

// mirror-paired column map:
// block b: cols {8b..8b+7} + mirrors; block 0 additionally owns cols 0,128.
static __device__ __forceinline__ int colmap(int b, int c) {
    if (c < 8) return 8 * b + c;
    if (b == 0) return (c == 15) ? 128 : 241 + c;   // 249..255, 128
    return 241 - 8 * b + c;                          // 249-8b .. 256-8b
}
static __device__ __forceinline__ int mircol(int b, int c) {
    return (b == 0) ? ((c == 0) ? 0 : (c == 15) ? 15 : 15 - c) : (15 - c);
}

// ---------------- pass 1: 256-pt FFT over t1 + inter twiddle ---------------
// FWD=1: rows [0,256) from x, linear t2.  FWD=0: inverse from g_So, columns
// mirror-paired so each spectrum value is read from global exactly once.
template <int FWD>
__global__ __launch_bounds__(256) void k_pass1(const float2* __restrict__ x) {
    __shared__ __half2 sm[4352];
    __shared__ float2 tw256[256];
    int tid = threadIdx.x;
    int c = tid & 15, s = tid >> 4;
    int row = blockIdx.y;
    int t2 = FWD ? (blockIdx.x * 16 + c) : colmap(blockIdx.x, c);
    tw256[tid] = g_twM[tid << 8];

    float2 r[16];
    if (FWD) {
        const float2* xr = x + (size_t)row * 32768;
        #pragma unroll
        for (int a = 0; a < 16; a++)
            r[a] = (a < 8) ? xr[(a * 16 + s) * 256 + t2]
                           : make_float2(0.f, 0.f);
        __syncthreads();
    } else {
        // inverse packed input from g_So (conj trick, /M), specialized halves.
        // Lower half loaded from global and stashed raw in smem; upper half
        // (mirror bins) read from the paired column's stash.
        const __half2* sr = g_So + (size_t)row * KEEP;
        const float hinv = 0.5f / 65536.0f;
        __half2 Sh[8];
        #pragma unroll
        for (int a = 0; a < 8; a++)
            Sh[a] = sr[(a * 16 + s) * 256 + t2];
        #pragma unroll
        for (int a = 0; a < 8; a++)
            sm[SMI(a * 16 + s, c)] = Sh[a];
        __syncthreads();

        #pragma unroll
        for (int a = 0; a < 8; a++) {
            int k = (a * 16 + s) * 256 + t2;
            float2 S = __half22float2(Sh[a]);
            float2 T = g_tw2M[k];                 // Tc = (T.x, -T.y)
            float Ox = fmaf(T.x, S.x,  T.y * S.y);
            float Oy = fmaf(T.x, S.y, -(T.y * S.x));
            r[a] = make_float2((S.x - Oy) * hinv, -(S.y + Ox) * hinv);
        }
        int cm = mircol(blockIdx.x, c);
        #pragma unroll
        for (int a = 8; a < 16; a++) {
            int k = (a * 16 + s) * 256 + t2;
            float2 Sm;
            if (t2 == 0) {
                // column 0 self-mirror uses j = 256 - t1 (incl. j=128): global
                Sm = ldc(sr + (M_FFT - k));
            } else {
                // j = 255 - t1 = (15-a)*16 + (15-s), column cm
                Sm = __half22float2(sm[SMI((15 - a) * 16 + (15 - s), cm)]);
            }
            float2 T = g_tw2M[k];
            float Ox = fmaf(-T.x, Sm.x,  T.y * Sm.y);
            float Oy = fmaf( T.x, Sm.y,  T.y * Sm.x);
            r[a] = make_float2((Sm.x - Oy) * hinv, (Sm.y - Ox) * hinv);
        }
        __syncthreads();   // protect sm before FFT reuse
    }

    fft16(r);
    #pragma unroll
    for (int p = 0; p < 16; p++)
        stc(&sm[SMI(p * 16 + s, c)], cmul(r[p], tw256[s * p]));
    __syncthreads();
    #pragma unroll
    for (int b = 0; b < 16; b++)
        r[b] = ldc(&sm[SMI(s * 16 + b, c)]);
    fft16(r);                                // r[q] = X[16q + s]  (k1)

    float2 cur = g_twM[(s * t2) & (M_FFT - 1)];
    float2 stp = g_twM[(t2 << 4) & (M_FFT - 1)];
    __half2* dst = g_B + (size_t)row * M_FFT;
    #pragma unroll
    for (int q = 0; q < 16; q++) {
        int k1 = q * 16 + s;
        stc(dst + k1 * 256 + t2, cmul(r[q], cur));
        cur = cmul(cur, stp);
    }
}

// ---------------- forward pass 2: FFT over t2 + in-block Hermitian unpack --
// Block columns are mirror-paired; writes unpacked X (bins 0..32768) to g_Sx.
// W rows (>= NROWS_X): staging synthesized analytically from w (delta row).
__global__ __launch_bounds__(256) void k_pass2f(const float2* __restrict__ w) {
    __shared__ __half2 sm[4352];
    __shared__ float2 tw256[256];
    int tid = threadIdx.x;
    int c = tid & 15, s = tid >> 4;
    int row = blockIdx.y;
    int b = blockIdx.x;
    tw256[tid] = g_twM[tid << 8];

    if (row >= NROWS_X) {
        // synthesize staging for the delta row (uniform branch per block)
        float2 z = make_float2(0.f, 0.f);
        if (tid < 64) z = w[(size_t)(row - NROWS_X) * 64 + tid];
        #pragma unroll
        for (int it = 0; it < 16; it++) {
            int k1 = colmap(b, it);
            float2 v = make_float2(0.f, 0.f);
            if (tid < 64)
                v = cmul(z, g_twM[(k1 * tid) & (M_FFT - 1)]);
            stc(&sm[SMI(tid, it)], v);
        }
    } else {
        const __half2* src = g_B + (size_t)row * M_FFT;
        #pragma unroll
        for (int it = 0; it < 16; it++)
            sm[SMI(tid, it)] = src[colmap(b, it) * 256 + tid];
    }
    __syncthreads();

    float2 r[16];
    #pragma unroll
    for (int a = 0; a < 16; a++)
        r[a] = ldc(&sm[SMI(a * 16 + s, c)]);
    fft16(r);
    __syncthreads();
    #pragma unroll
    for (int p = 0; p < 16; p++)
        stc(&sm[SMI(p * 16 + s, c)], cmul(r[p], tw256[s * p]));
    __syncthreads();
    #pragma unroll
    for (int bq = 0; bq < 16; bq++)
        r[bq] = ldc(&sm[SMI(s * 16 + bq, c)]);
    fft16(r);                                // r[q] = Z[k2=16q+s][col c]
    __syncthreads();

    // stash only k2 >= 128 (the mirrors of the written bins): slot k2-128
    #pragma unroll
    for (int q = 8; q < 16; q++)
        stc(&sm[SMI((q - 8) * 16 + s, c)], r[q]);
    __syncthreads();

    int k1 = colmap(b, c);
    int cm = mircol(b, c);
    __half2* dst = g_Sx + (size_t)row * KEEP;
    #pragma unroll
    for (int q = 0; q < 8; q++) {            // k2 in 0..127 -> bins <= 32767
        int k2 = q * 16 + s;
        int bin = k2 * 256 + k1;
        float2 Zk = r[q];
        int mk2 = (k1 == 0) ? ((256 - k2) & 255) : (255 - k2);
        float2 Zm = (bin == 0) ? r[0] : ldc(&sm[SMI(mk2 - 128, cm)]);
        float2 zmc = make_float2(Zm.x, -Zm.y);
        float2 E2 = padd(Zk, zmc);
        float2 D  = psub(Zk, zmc);
        float2 TD = cmul(g_tw2M[bin], D);
        float2 S  = padd(E2, make_float2(TD.y, -TD.x));
        stc(dst + bin, make_float2(0.5f * S.x, 0.5f * S.y));
    }
    if (b == 0 && c == 0 && s == 0) {        // bin 32768: k2=128, self-mirror
        float2 Zk = r[8];
        float2 zmc = make_float2(Zk.x, -Zk.y);
        float2 E2 = padd(Zk, zmc);
        float2 D  = psub(Zk, zmc);
        float2 TD = cmul(g_tw2M[32768], D);
        float2 S  = padd(E2, make_float2(TD.y, -TD.x));
        stc(dst + 32768, make_float2(0.5f * S.x, 0.5f * S.y));
    }
}

// ---------------- inverse pass 2: FFT over t2, depack + bias ---------------
__global__ __launch_bounds__(256) void k_pass2inv(float* __restrict__ out,
                                                  const float* __restrict__ bias) {
    __shared__ __half2 sm[4352];
    __shared__ float2 tw256[256];
    int tid = threadIdx.x;
    int c = tid & 15, s = tid >> 4;
    int row = blockIdx.y;
    int k1b = blockIdx.x * 16;
    tw256[tid] = g_twM[tid << 8];

    const __half2* src = g_B + (size_t)row * M_FFT + (size_t)k1b * 256;
    #pragma unroll
    for (int it = 0; it < 16; it++)
        sm[SMI(tid, it)] = src[it * 256 + tid];
    __syncthreads();

    float2 r[16];
    #pragma unroll
    for (int a = 0; a < 16; a++)
        r[a] = ldc(&sm[SMI(a * 16 + s, c)]);
    fft16(r);
    __syncthreads();
    #pragma unroll
    for (int p = 0; p < 16; p++)
        stc(&sm[SMI(p * 16 + s, c)], cmul(r[p], tw256[s * p]));
    __syncthreads();
    #pragma unroll
    for (int b = 0; b < 16; b++)
        r[b] = ldc(&sm[SMI(s * 16 + b, c)]);
    fft16(r);                                // r[q] = X[16q + s]  (k2)

    float bv = bias[row & 15];
    float* orow = out + (size_t)row * OUT_W;
    if ((row & 1) == 0) {
        // even row: orow is 8B-aligned (OUT_W odd, row even) -> STG.64 pairs
        #pragma unroll
        for (int q = 0; q < 16; q++) {
            int m = (q * 16 + s) * 256 + k1b + c;
            int t = 2 * m;
            if (t + 1 < OUT_W) {
                *(float2*)(orow + t) = make_float2(r[q].x + bv, -r[q].y + bv);
            } else if (t < OUT_W) {
                orow[t] = r[q].x + bv;
            }
        }
    } else {
        // odd row: base only 4B-aligned -> scalar stores
        #pragma unroll
        for (int q = 0; q < 16; q++) {
            int m = (q * 16 + s) * 256 + k1b + c;
            int t = 2 * m;
            if (t < OUT_W)     orow[t]     =  r[q].x + bv;
            if (t + 1 < OUT_W) orow[t + 1] = -r[q].y + bv;
        }
    }
}

// ---------------- einsum over c: 4n x 4f register tile, packed FMA ---------
// KT=16 bins/block; single contiguous load stream from unpacked g_Sx.
#define KT 16
__global__ __launch_bounds__(256) void k_einsum() {
    __shared__ float2 XsF[NROWS_X * KT + 64];    // skewed: slot=16r+kq+(r>>3)
    __shared__ float2 Ws[NROWS_W][KT];
    int k0 = blockIdx.x * KT;
    int tid = threadIdx.x;

    // load phase: 24 contiguous predicated loads (no mirrors, no unpack)
    #pragma unroll
    for (int hb = 0; hb < 2; hb++) {
        __half2 bx[12];
        #pragma unroll
        for (int ii = 0; ii < 12; ii++) {
            int idx = (hb * 12 + ii) * 256 + tid;
            int r = idx >> 4, kq = idx & 15;
            int kg2 = k0 + kq;
            bx[ii] = (kg2 < KEEP) ? g_Sx[(size_t)r * KEEP + kg2]
                                  : __float2half2_rn(0.f);
        }
        #pragma unroll
        for (int ii = 0; ii < 12; ii++) {
            int idx = (hb * 12 + ii) * 256 + tid;
            int r = idx >> 4, kq = idx & 15;
            float2 X = __half22float2(bx[ii]);
            if (r < NROWS_X) XsF[r * 16 + kq + (r >> 3)] = X;
            else             Ws[r - NROWS_X][kq] = X;
        }
    }
    __syncthreads();

    int kk = tid & 7;
    int nb = ((tid >> 3) & 7) * 4;    // n base (0..28)
    int fb = (tid >> 6) * 4;          // f base (0..12)

    #pragma unroll
    for (int p = 0; p < 2; p++) {
        int kq = kk + 8 * p;
        int kg = k0 + kq;

        unsigned long long acc[4][4];
        #pragma unroll
        for (int j = 0; j < 4; j++)
            #pragma unroll
            for (int i = 0; i < 4; i++) acc[j][i] = 0ULL;

        #pragma unroll
        for (int cc = 0; cc < 8; cc++) {
            unsigned long long pb1[4], pb2[4];
            #pragma unroll
            for (int i = 0; i < 4; i++) {
                float2 b = Ws[(fb + i) * 8 + cc][kq];
                float nby = -b.y;
                asm("mov.b64 %0, {%1,%2};" : "=l"(pb1[i]) : "f"(b.x), "f"(nby));
                asm("mov.b64 %0, {%1,%2};" : "=l"(pb2[i]) : "f"(b.y), "f"(b.x));
            }
            #pragma unroll
            for (int j = 0; j < 4; j++) {
                int rr = (nb + j) * 8 + cc;
                float2 a = XsF[rr * 16 + kq + (rr >> 3)];
                unsigned long long sax, say;
                asm("mov.b64 %0, {%1,%1};" : "=l"(sax) : "f"(a.x));
                asm("mov.b64 %0, {%1,%1};" : "=l"(say) : "f"(a.y));
                #pragma unroll
                for (int i = 0; i < 4; i++) {
                    asm("fma.rn.f32x2 %0, %1, %2, %0;" : "+l"(acc[j][i])
                        : "l"(pb1[i]), "l"(sax));
                    asm("fma.rn.f32x2 %0, %1, %2, %0;" : "+l"(acc[j][i])
                        : "l"(pb2[i]), "l"(say));
                }
            }
        }

        if (kg < KEEP) {
            #pragma unroll
            for (int j = 0; j < 4; j++)
                #pragma unroll
                for (int i = 0; i < 4; i++) {
                    float2 o;
                    asm("mov.b64 {%0,%1}, %2;" : "=f"(o.x), "=f"(o.y)
                        : "l"(acc[j][i]));
                    stc(g_So + (size_t)((nb + j) * 16 + fb + i) * KEEP + kg, o);
                }
        }
    }
}

// ============================================================================
extern "C" void kernel_launch(void* const* d_in, const int* in_sizes, int n_in,
                              void* d_out, int out_size) {
    const float2* x    = (const float2*)d_in[0];
    const float2* w    = (const float2*)d_in[1];
    const float*  bias = (const float*)d_in[2];
    float* out = (float*)d_out;

    k_init_tw<<<(M_FFT + 255) / 256, 256>>>();

    // forward: pass1 on x rows only; pass2 (unpack + W synthesis) on all
    { dim3 g(16, NROWS_X); k_pass1<1><<<g, 256>>>(x); }
    { dim3 g(16, NROWS_F); k_pass2f<<<g, 256>>>(w); }

    // pointwise contraction over c
    k_einsum<<<(KEEP + KT - 1) / KT, 256>>>();

    // inverse: pass1 (mirror-shared unpack), pass2 (depack + bias)
    { dim3 g(16, NROWS_O); k_pass1<0><<<g, 256>>>(nullptr); }
    { dim3 g(16, NROWS_O); k_pass2inv<<<g, 256>>>(out, bias); }
}

// round 17
// speedup vs baseline: 1.0843x; 1.0843x over previous
#include <cuda_runtime.h>
#include <cuda_fp16.h>

// ============================================================================
// Conv1Dfft via packed-real four-step FFT (M = 65536 = 256 x 256),
// register 16x16 FFT, fp16 global + fp16 smem intermediates, f32x2 math.
// Forward pass2 unpacks to rfft bins in-block; W spectrum synthesized in
// pass2 via twiddle recurrence; parity-vectorized output stores.
// ============================================================================

#define M_FFT   65536
#define KEEP    32769          // bins 0..32768 kept (== M/2+1)
#define NROWS_X 256            // 32 n * 8 c
#define NROWS_W 128            // 16 f * 8 c
#define NROWS_F 384
#define NROWS_O 512            // 32 n * 16 f
#define OUT_W   65409

// ---------------- scratch (device globals; allocation-free) ----------------
__device__ __half2 g_Sx[(size_t)NROWS_F * KEEP];   // unpacked fwd spectra X
__device__ __half2 g_B[(size_t)NROWS_O * M_FFT];   // pass1 out (x fwd + inverse)
__device__ __half2 g_So[(size_t)NROWS_O * KEEP];   // product spectra
__device__ float2 g_twM[M_FFT];                    // e^{-2pi i j / 65536}
__device__ float2 g_tw2M[M_FFT];                   // e^{-2pi i j / 131072}

// ---------------- packed f32x2 complex helpers -----------------------------
static __device__ __forceinline__ float2 padd(float2 a, float2 b) {
    unsigned long long ua, ub, ur;
    asm("mov.b64 %0, {%1,%2};" : "=l"(ua) : "f"(a.x), "f"(a.y));
    asm("mov.b64 %0, {%1,%2};" : "=l"(ub) : "f"(b.x), "f"(b.y));
    asm("add.rn.f32x2 %0, %1, %2;" : "=l"(ur) : "l"(ua), "l"(ub));
    float2 o;
    asm("mov.b64 {%0,%1}, %2;" : "=f"(o.x), "=f"(o.y) : "l"(ur));
    return o;
}
static __device__ __forceinline__ float2 psub(float2 a, float2 b) {
    unsigned long long ua, ub, ur;
    const unsigned long long NEG1 = 0xBF800000BF800000ULL;  // (-1.f, -1.f)
    asm("mov.b64 %0, {%1,%2};" : "=l"(ua) : "f"(a.x), "f"(a.y));
    asm("mov.b64 %0, {%1,%2};" : "=l"(ub) : "f"(b.x), "f"(b.y));
    asm("fma.rn.f32x2 %0, %1, %2, %3;" : "=l"(ur) : "l"(ub), "l"(NEG1), "l"(ua));
    float2 o;
    asm("mov.b64 {%0,%1}, %2;" : "=f"(o.x), "=f"(o.y) : "l"(ur));
    return o;
}
static __device__ __forceinline__ float2 cmul(float2 a, float2 b) {
    return make_float2(fmaf(a.x, b.x, -(a.y * b.y)),
                       fmaf(a.x, b.y,   a.y * b.x));
}
static __device__ __forceinline__ float2 ldc(const __half2* p) {
    return __half22float2(*p);
}
static __device__ __forceinline__ void stc(__half2* p, float2 v) {
    *p = __float22half2_rn(v);
}

// ---------------- twiddle tables (fp32 sincospif, exact args) --------------
__global__ void k_init_tw() {
    int i = blockIdx.x * blockDim.x + threadIdx.x;
    if (i < M_FFT) {
        float s, c;
        sincospif(-(float)i / 32768.0f, &s, &c);
        g_twM[i] = make_float2(c, s);
        sincospif(-(float)i / 65536.0f, &s, &c);
        g_tw2M[i] = make_float2(c, s);
    }
}

// ---------------- 4-pt DFT on packed complex -------------------------------
static __device__ __forceinline__ void dft4(float2 x0, float2 x1, float2 x2,
                                            float2 x3, float2& y0, float2& y1,
                                            float2& y2, float2& y3) {
    float2 s0 = padd(x0, x2);
    float2 d0 = psub(x0, x2);
    float2 s1 = padd(x1, x3);
    float2 d1 = psub(x1, x3);
    y0 = padd(s0, s1);
    y2 = psub(s0, s1);
    float2 sw = make_float2(d1.y, -d1.x);   // -i*d1
    y1 = padd(d0, sw);
    y3 = psub(d0, sw);
}

// ---------------- 16-pt DFT in registers (radix-4 x radix-4) ---------------
__device__ __forceinline__ void fft16(float2 r[16]) {
    const float C1 = 0.9238795325112867f;
    const float S1 = 0.3826834323650898f;
    const float R2 = 0.7071067811865476f;
    float2 t[16];
    {
        float2 y0, y1, y2, y3;
        dft4(r[0], r[4], r[8], r[12], y0, y1, y2, y3);
        t[0] = y0; t[4] = y1; t[8] = y2; t[12] = y3;
    }
    {
        float2 y0, y1, y2, y3;
        dft4(r[1], r[5], r[9], r[13], y0, y1, y2, y3);
        t[1]  = y0;
        t[5]  = cmul(y1, make_float2( C1, -S1));
        t[9]  = cmul(y2, make_float2( R2, -R2));
        t[13] = cmul(y3, make_float2( S1, -C1));
    }
    {
        float2 y0, y1, y2, y3;
        dft4(r[2], r[6], r[10], r[14], y0, y1, y2, y3);
        t[2]  = y0;
        t[6]  = cmul(y1, make_float2( R2, -R2));
        t[10] = make_float2( y2.y, -y2.x);
        t[14] = cmul(y3, make_float2(-R2, -R2));
    }
    {
        float2 y0, y1, y2, y3;
        dft4(r[3], r[7], r[11], r[15], y0, y1, y2, y3);
        t[3]  = y0;
        t[7]  = cmul(y1, make_float2( S1, -C1));
        t[11] = cmul(y2, make_float2(-R2, -R2));
        t[15] = cmul(y3, make_float2(-C1,  S1));
    }
    #pragma unroll
    for (int p1 = 0; p1 < 4; p1++) {
        float2 y0, y1, y2, y3;
        dft4(t[4 * p1], t[4 * p1 + 1], t[4 * p1 + 2], t[4 * p1 + 3],
             y0, y1, y2, y3);
        r[p1] = y0; r[4 + p1] = y1; r[8 + p1] = y2; r[12 + p1] = y3;
    }
}

// pad-17 smem slot for pass-kernel tiles
#define SMI(u, c) ((u) * 17 + (c))

// mirror-paired column map for forward pass2:
// block b: cols {8b..8b+7} + mirrors; block 0 additionally owns cols 0,128.
static __device__ __forceinline__ int colmap(int b, int c) {
    if (c < 8) return 8 * b + c;
    if (b == 0) return (c == 15) ? 128 : 241 + c;   // 249..255, 128
    return 241 - 8 * b + c;                          // 249-8b .. 256-8b
}

// ---------------- pass 1: 256-pt FFT over t1 + inter twiddle ---------------
// FWD=1: rows [0,256) from x.  FWD=0: inverse from g_So (rows [0,512)).
template <int FWD>
__global__ __launch_bounds__(256) void k_pass1(const float2* __restrict__ x) {
    __shared__ __half2 sm[4352];
    __shared__ float2 tw256[256];
    int tid = threadIdx.x;
    int c = tid & 15, s = tid >> 4;
    int t2 = blockIdx.x * 16 + c;
    int row = blockIdx.y;
    tw256[tid] = g_twM[tid << 8];

    float2 r[16];
    if (FWD) {
        const float2* xr = x + (size_t)row * 32768;
        #pragma unroll
        for (int a = 0; a < 16; a++)
            r[a] = (a < 8) ? xr[(a * 16 + s) * 256 + t2]
                           : make_float2(0.f, 0.f);
    } else {
        // inverse packed input from g_So (conj trick, /M), specialized halves.
        const __half2* sr = g_So + (size_t)row * KEEP;
        const float hinv = 0.5f / 65536.0f;
        float2 S[8];
        #pragma unroll
        for (int a = 0; a < 8; a++)
            S[a] = ldc(sr + (a * 16 + s) * 256 + t2);
        #pragma unroll
        for (int a = 0; a < 8; a++) {
            int k = (a * 16 + s) * 256 + t2;
            float2 T = g_tw2M[k];                 // Tc = (T.x, -T.y)
            float Ox = fmaf(T.x, S[a].x,  T.y * S[a].y);
            float Oy = fmaf(T.x, S[a].y, -(T.y * S[a].x));
            r[a] = make_float2((S[a].x - Oy) * hinv, -(S[a].y + Ox) * hinv);
        }
        #pragma unroll
        for (int a = 8; a < 16; a++)
            S[a - 8] = ldc(sr + (M_FFT - ((a * 16 + s) * 256 + t2)));
        #pragma unroll
        for (int a = 8; a < 16; a++) {
            int k = (a * 16 + s) * 256 + t2;
            float2 Sm = S[a - 8];
            float2 T = g_tw2M[k];
            float Ox = fmaf(-T.x, Sm.x,  T.y * Sm.y);
            float Oy = fmaf( T.x, Sm.y,  T.y * Sm.x);
            r[a] = make_float2((Sm.x - Oy) * hinv, (Sm.y - Ox) * hinv);
        }
    }
    __syncthreads();

    fft16(r);
    #pragma unroll
    for (int p = 0; p < 16; p++)
        stc(&sm[SMI(p * 16 + s, c)], cmul(r[p], tw256[s * p]));
    __syncthreads();
    #pragma unroll
    for (int b = 0; b < 16; b++)
        r[b] = ldc(&sm[SMI(s * 16 + b, c)]);
    fft16(r);                                // r[q] = X[16q + s]  (k1)

    float2 cur = g_twM[(s * t2) & (M_FFT - 1)];
    float2 stp = g_twM[(t2 << 4) & (M_FFT - 1)];
    __half2* dst = g_B + (size_t)row * M_FFT;
    #pragma unroll
    for (int q = 0; q < 16; q++) {
        int k1 = q * 16 + s;
        stc(dst + k1 * 256 + t2, cmul(r[q], cur));
        cur = cmul(cur, stp);
    }
}

// ---------------- forward pass 2: FFT over t2 + in-block Hermitian unpack --
// Block columns are mirror-paired; writes unpacked X (bins 0..32768) to g_Sx.
// W rows (>= NROWS_X): staging synthesized analytically from w (delta row)
// with a w^tid twiddle recurrence (2 base loads instead of 16 scattered).
__global__ __launch_bounds__(256) void k_pass2f(const float2* __restrict__ w) {
    __shared__ __half2 sm[4352];
    __shared__ float2 tw256[256];
    int tid = threadIdx.x;
    int c = tid & 15, s = tid >> 4;
    int row = blockIdx.y;
    int b = blockIdx.x;
    tw256[tid] = g_twM[tid << 8];

    if (row >= NROWS_X) {
        // synthesize staging for the delta row (uniform branch per block):
        //   Z1[k1][t2=tid] = z[tid] * w_M^{k1*tid}
        // colmap k1 increments by 1 per it within each half -> recurrence.
        if (tid < 64) {
            float2 z = w[(size_t)(row - NROWS_X) * 64 + tid];
            float2 step = g_twM[tid];
            float2 cur = g_twM[(8 * b * tid) & (M_FFT - 1)];
            #pragma unroll
            for (int it = 0; it < 8; it++) {     // k1 = 8b + it
                stc(&sm[SMI(tid, it)], cmul(z, cur));
                cur = cmul(cur, step);
            }
            int k1u = (b == 0) ? 249 : (249 - 8 * b);
            cur = g_twM[(k1u * tid) & (M_FFT - 1)];
            #pragma unroll
            for (int it = 8; it < 16; it++) {    // k1 = k1u + (it-8)
                if (b == 0 && it == 15)          // block 0 col 15 is k1=128
                    cur = g_twM[(128 * tid) & (M_FFT - 1)];
                stc(&sm[SMI(tid, it)], cmul(z, cur));
                cur = cmul(cur, step);
            }
        } else {
            __half2 zz = __float2half2_rn(0.f);
            #pragma unroll
            for (int it = 0; it < 16; it++)
                sm[SMI(tid, it)] = zz;
        }
    } else {
        const __half2* src = g_B + (size_t)row * M_FFT;
        #pragma unroll
        for (int it = 0; it < 16; it++)
            sm[SMI(tid, it)] = src[colmap(b, it) * 256 + tid];
    }
    __syncthreads();

    float2 r[16];
    #pragma unroll
    for (int a = 0; a < 16; a++)
        r[a] = ldc(&sm[SMI(a * 16 + s, c)]);
    fft16(r);
    __syncthreads();
    #pragma unroll
    for (int p = 0; p < 16; p++)
        stc(&sm[SMI(p * 16 + s, c)], cmul(r[p], tw256[s * p]));
    __syncthreads();
    #pragma unroll
    for (int bq = 0; bq < 16; bq++)
        r[bq] = ldc(&sm[SMI(s * 16 + bq, c)]);
    fft16(r);                                // r[q] = Z[k2=16q+s][col c]
    __syncthreads();

    // stash only k2 >= 128 (the mirrors of the written bins): slot k2-128
    #pragma unroll
    for (int q = 8; q < 16; q++)
        stc(&sm[SMI((q - 8) * 16 + s, c)], r[q]);
    __syncthreads();

    int k1 = colmap(b, c);
    int cm = (b == 0) ? ((c == 0) ? 0 : (c == 15) ? 15 : 15 - c) : (15 - c);
    __half2* dst = g_Sx + (size_t)row * KEEP;
    #pragma unroll
    for (int q = 0; q < 8; q++) {            // k2 in 0..127 -> bins <= 32767
        int k2 = q * 16 + s;
        int bin = k2 * 256 + k1;
        float2 Zk = r[q];
        int mk2 = (k1 == 0) ? ((256 - k2) & 255) : (255 - k2);
        float2 Zm = (bin == 0) ? r[0] : ldc(&sm[SMI(mk2 - 128, cm)]);
        float2 zmc = make_float2(Zm.x, -Zm.y);
        float2 E2 = padd(Zk, zmc);
        float2 D  = psub(Zk, zmc);
        float2 TD = cmul(g_tw2M[bin], D);
        float2 S  = padd(E2, make_float2(TD.y, -TD.x));
        stc(dst + bin, make_float2(0.5f * S.x, 0.5f * S.y));
    }
    if (b == 0 && c == 0 && s == 0) {        // bin 32768: k2=128, self-mirror
        float2 Zk = r[8];
        float2 zmc = make_float2(Zk.x, -Zk.y);
        float2 E2 = padd(Zk, zmc);
        float2 D  = psub(Zk, zmc);
        float2 TD = cmul(g_tw2M[32768], D);
        float2 S  = padd(E2, make_float2(TD.y, -TD.x));
        stc(dst + 32768, make_float2(0.5f * S.x, 0.5f * S.y));
    }
}

// ---------------- inverse pass 2: FFT over t2, depack + bias ---------------
__global__ __launch_bounds__(256) void k_pass2inv(float* __restrict__ out,
                                                  const float* __restrict__ bias) {
    __shared__ __half2 sm[4352];
    __shared__ float2 tw256[256];
    int tid = threadIdx.x;
    int c = tid & 15, s = tid >> 4;
    int row = blockIdx.y;
    int k1b = blockIdx.x * 16;
    tw256[tid] = g_twM[tid << 8];

    const __half2* src = g_B + (size_t)row * M_FFT + (size_t)k1b * 256;
    #pragma unroll
    for (int it = 0; it < 16; it++)
        sm[SMI(tid, it)] = src[it * 256 + tid];
    __syncthreads();

    float2 r[16];
    #pragma unroll
    for (int a = 0; a < 16; a++)
        r[a] = ldc(&sm[SMI(a * 16 + s, c)]);
    fft16(r);
    __syncthreads();
    #pragma unroll
    for (int p = 0; p < 16; p++)
        stc(&sm[SMI(p * 16 + s, c)], cmul(r[p], tw256[s * p]));
    __syncthreads();
    #pragma unroll
    for (int b = 0; b < 16; b++)
        r[b] = ldc(&sm[SMI(s * 16 + b, c)]);
    fft16(r);                                // r[q] = X[16q + s]  (k2)

    float bv = bias[row & 15];
    float* orow = out + (size_t)row * OUT_W;
    if ((row & 1) == 0) {
        // even row: orow is 8B-aligned (OUT_W odd, row even) -> STG.64 pairs
        #pragma unroll
        for (int q = 0; q < 16; q++) {
            int m = (q * 16 + s) * 256 + k1b + c;
            int t = 2 * m;
            if (t + 1 < OUT_W) {
                *(float2*)(orow + t) = make_float2(r[q].x + bv, -r[q].y + bv);
            } else if (t < OUT_W) {
                orow[t] = r[q].x + bv;
            }
        }
    } else {
        // odd row: base only 4B-aligned -> scalar stores
        #pragma unroll
        for (int q = 0; q < 16; q++) {
            int m = (q * 16 + s) * 256 + k1b + c;
            int t = 2 * m;
            if (t < OUT_W)     orow[t]     =  r[q].x + bv;
            if (t + 1 < OUT_W) orow[t + 1] = -r[q].y + bv;
        }
    }
}

// ---------------- einsum over c: 4n x 4f register tile, packed FMA ---------
// KT=16 bins/block; single contiguous load stream from unpacked g_Sx.
#define KT 16
__global__ __launch_bounds__(256) void k_einsum() {
    __shared__ float2 XsF[NROWS_X * KT + 64];    // skewed: slot=16r+kq+(r>>3)
    __shared__ float2 Ws[NROWS_W][KT];
    int k0 = blockIdx.x * KT;
    int tid = threadIdx.x;

    // load phase: 24 contiguous predicated loads (no mirrors, no unpack)
    #pragma unroll
    for (int hb = 0; hb < 2; hb++) {
        __half2 bx[12];
        #pragma unroll
        for (int ii = 0; ii < 12; ii++) {
            int idx = (hb * 12 + ii) * 256 + tid;
            int r = idx >> 4, kq = idx & 15;
            int kg2 = k0 + kq;
            bx[ii] = (kg2 < KEEP) ? g_Sx[(size_t)r * KEEP + kg2]
                                  : __float2half2_rn(0.f);
        }
        #pragma unroll
        for (int ii = 0; ii < 12; ii++) {
            int idx = (hb * 12 + ii) * 256 + tid;
            int r = idx >> 4, kq = idx & 15;
            float2 X = __half22float2(bx[ii]);
            if (r < NROWS_X) XsF[r * 16 + kq + (r >> 3)] = X;
            else             Ws[r - NROWS_X][kq] = X;
        }
    }
    __syncthreads();

    int kk = tid & 7;
    int nb = ((tid >> 3) & 7) * 4;    // n base (0..28)
    int fb = (tid >> 6) * 4;          // f base (0..12)

    #pragma unroll
    for (int p = 0; p < 2; p++) {
        int kq = kk + 8 * p;
        int kg = k0 + kq;

        unsigned long long acc[4][4];
        #pragma unroll
        for (int j = 0; j < 4; j++)
            #pragma unroll
            for (int i = 0; i < 4; i++) acc[j][i] = 0ULL;

        #pragma unroll
        for (int cc = 0; cc < 8; cc++) {
            unsigned long long pb1[4], pb2[4];
            #pragma unroll
            for (int i = 0; i < 4; i++) {
                float2 b = Ws[(fb + i) * 8 + cc][kq];
                float nby = -b.y;
                asm("mov.b64 %0, {%1,%2};" : "=l"(pb1[i]) : "f"(b.x), "f"(nby));
                asm("mov.b64 %0, {%1,%2};" : "=l"(pb2[i]) : "f"(b.y), "f"(b.x));
            }
            #pragma unroll
            for (int j = 0; j < 4; j++) {
                int rr = (nb + j) * 8 + cc;
                float2 a = XsF[rr * 16 + kq + (rr >> 3)];
                unsigned long long sax, say;
                asm("mov.b64 %0, {%1,%1};" : "=l"(sax) : "f"(a.x));
                asm("mov.b64 %0, {%1,%1};" : "=l"(say) : "f"(a.y));
                #pragma unroll
                for (int i = 0; i < 4; i++) {
                    asm("fma.rn.f32x2 %0, %1, %2, %0;" : "+l"(acc[j][i])
                        : "l"(pb1[i]), "l"(sax));
                    asm("fma.rn.f32x2 %0, %1, %2, %0;" : "+l"(acc[j][i])
                        : "l"(pb2[i]), "l"(say));
                }
            }
        }

        if (kg < KEEP) {
            #pragma unroll
            for (int j = 0; j < 4; j++)
                #pragma unroll
                for (int i = 0; i < 4; i++) {
                    float2 o;
                    asm("mov.b64 {%0,%1}, %2;" : "=f"(o.x), "=f"(o.y)
                        : "l"(acc[j][i]));
                    stc(g_So + (size_t)((nb + j) * 16 + fb + i) * KEEP + kg, o);
                }
        }
    }
}

// ============================================================================
extern "C" void kernel_launch(void* const* d_in, const int* in_sizes, int n_in,
                              void* d_out, int out_size) {
    const float2* x    = (const float2*)d_in[0];
    const float2* w    = (const float2*)d_in[1];
    const float*  bias = (const float*)d_in[2];
    float* out = (float*)d_out;

    k_init_tw<<<(M_FFT + 255) / 256, 256>>>();

    // forward: pass1 on x rows only; pass2 (unpack + W synthesis) on all
    { dim3 g(16, NROWS_X); k_pass1<1><<<g, 256>>>(x); }
    { dim3 g(16, NROWS_F); k_pass2f<<<g, 256>>>(w); }

    // pointwise contraction over c
    k_einsum<<<(KEEP + KT - 1) / KT, 256>>>();

    // inverse: pass1 with fused inverse-pack, pass2 with fused depack+bias
    { dim3 g(16, NROWS_O); k_pass1<0><<<g, 256>>>(nullptr); }
    { dim3 g(16, NROWS_O); k_pass2inv<<<g, 256>>>(out, bias); }
}